// round 14
// baseline (speedup 1.0000x reference)
#include <cuda_runtime.h>
#include <cuda_bf16.h>
#include <cstdint>

// ---------------------------------------------------------------------------
// Problem shape
// ---------------------------------------------------------------------------
#define N_BATCH 32
#define CH      64
#define HH      112
#define WW      112
#define PIX     (HH*WW)              // 12544
#define NX      (N_BATCH*CH*PIX)     // 25,690,112
#define NWELEM  (64*64*3*3)          // 36,864
#define NGROUPS ((NX + 35) / 36)     // 713,615

__device__ __align__(16) __nv_bfloat16 g_xt[NX];       // quantized x, NHWC
__device__ __align__(16) __nv_bfloat16 g_wk[9*64*64];  // [k][co][ci]
__device__ __align__(16) float2        g_scale[NGROUPS]; // {scl, inv}

#define SW128(off) ((off) ^ (((off) >> 3) & 0x70))

// ---------------------------------------------------------------------------
// Weights: fused BFP quantize + repack OIHW -> [k][co][ci]. 4 blocks.
// ---------------------------------------------------------------------------
__global__ __launch_bounds__(256)
void wquant_repack_kernel(const float4* __restrict__ src,
                          __nv_bfloat16* __restrict__ wk) {
    __shared__ float sMax[2304];
    __shared__ float sScl[256];
    __shared__ float sInv[256];
    const int tid = threadIdx.x;
    const int n4  = NWELEM / 4;      // 9216
    const long base = (long)blockIdx.x * 2304;

    float4 v[9];
    #pragma unroll
    for (int r = 0; r < 9; ++r) {
        long j = base + r * 256 + tid;
        float4 x = make_float4(0.f, 0.f, 0.f, 0.f);
        if (j < n4) x = src[j];
        v[r] = x;
        sMax[r * 256 + tid] =
            fmaxf(fmaxf(fabsf(x.x), fabsf(x.y)), fmaxf(fabsf(x.z), fabsf(x.w)));
    }
    __syncthreads();
    {
        float m = sMax[tid * 9];
        #pragma unroll
        for (int i = 1; i < 9; ++i) m = fmaxf(m, sMax[tid * 9 + i]);
        float scl = 0.f, inv = 0.f;
        if (m > 0.f) {
            float e = floorf(log2f(m));
            scl = exp2f(e - 7.f);
            inv = exp2f(7.f - e);
        }
        sScl[tid] = scl;
        sInv[tid] = inv;
    }
    __syncthreads();
    #pragma unroll
    for (int r = 0; r < 9; ++r) {
        long j = base + r * 256 + tid;
        if (j >= n4) continue;
        int g = (r * 256 + tid) / 9;
        float scl = sScl[g], inv = sInv[g];
        float q[4];
        q[0] = rintf(v[r].x * inv) * scl;
        q[1] = rintf(v[r].y * inv) * scl;
        q[2] = rintf(v[r].z * inv) * scl;
        q[3] = rintf(v[r].w * inv) * scl;
        #pragma unroll
        for (int e = 0; e < 4; ++e) {
            long f  = j * 4 + e;             // flat OIHW index
            int co  = (int)(f / 576);
            int rem = (int)(f - (long)co * 576);
            int ci  = rem / 9;
            int k   = rem - ci * 9;
            wk[k * 4096 + co * 64 + ci] = __float2bfloat16_rn(q[e]);
        }
    }
}

// ---------------------------------------------------------------------------
// Pass 1 (x): per-group scale computation only.
// ---------------------------------------------------------------------------
__global__ __launch_bounds__(256)
void bfp_scale_kernel(const float4* __restrict__ src, int n4, long ngroups,
                      float2* __restrict__ scale) {
    __shared__ float sMax[2304];
    const int tid = threadIdx.x;
    const long base = (long)blockIdx.x * 2304;

    #pragma unroll
    for (int r = 0; r < 9; ++r) {
        long j = base + r * 256 + tid;
        float4 x = make_float4(0.f, 0.f, 0.f, 0.f);
        if (j < n4) x = src[j];
        sMax[r * 256 + tid] =
            fmaxf(fmaxf(fabsf(x.x), fabsf(x.y)), fmaxf(fabsf(x.z), fabsf(x.w)));
    }
    __syncthreads();
    long g = (long)blockIdx.x * 256 + tid;
    if (g < ngroups) {
        float m = sMax[tid * 9];
        #pragma unroll
        for (int i = 1; i < 9; ++i) m = fmaxf(m, sMax[tid * 9 + i]);
        float scl = 0.f, inv = 0.f;
        if (m > 0.f) {
            float e = floorf(log2f(m));
            scl = exp2f(e - 7.f);
            inv = exp2f(7.f - e);
        }
        scale[g] = make_float2(scl, inv);
    }
}

// ---------------------------------------------------------------------------
// Pass 2 (x): fused quantize + NCHW->NHWC transpose (scalar smem stores).
// ---------------------------------------------------------------------------
__global__ __launch_bounds__(256)
void quant_transpose_kernel(const float4* __restrict__ x,
                            const float2* __restrict__ scale,
                            __nv_bfloat16* __restrict__ dst) {
    __shared__ __nv_bfloat16 s[64 * 65];
    const int tid = threadIdx.x;
    const int n   = blockIdx.y;
    const int p0  = blockIdx.x * 64;

    #pragma unroll
    for (int it = 0; it < 4; ++it) {
        int idx = it * 256 + tid;
        int ci = idx >> 4;
        int c  = idx & 15;
        long f4 = (long)(n * 64 + ci) * (PIX / 4) + (p0 >> 2) + c;
        float4 v = x[f4];
        float2 si = scale[f4 / 9];
        float scl = si.x, inv = si.y;
        __nv_bfloat16* sp = &s[ci * 65 + c * 4];
        sp[0] = __float2bfloat16_rn(rintf(v.x * inv) * scl);
        sp[1] = __float2bfloat16_rn(rintf(v.y * inv) * scl);
        sp[2] = __float2bfloat16_rn(rintf(v.z * inv) * scl);
        sp[3] = __float2bfloat16_rn(rintf(v.w * inv) * scl);
    }
    __syncthreads();
    #pragma unroll
    for (int it = 0; it < 2; ++it) {
        int idx = it * 256 + tid;
        int pix = idx >> 3;
        int c   = idx & 7;
        uint4 v;
        __nv_bfloat16* e = (__nv_bfloat16*)&v;
        #pragma unroll
        for (int j = 0; j < 8; ++j) e[j] = s[(c * 8 + j) * 65 + pix];
        *(uint4*)(dst + ((size_t)(n * PIX + p0 + pix)) * 64 + c * 8) = v;
    }
}

// ---------------------------------------------------------------------------
// mma.sync / cp.async helpers
// ---------------------------------------------------------------------------
__device__ __forceinline__ void ldsm_x4(uint32_t& r0, uint32_t& r1,
                                        uint32_t& r2, uint32_t& r3,
                                        uint32_t addr) {
    asm volatile("ldmatrix.sync.aligned.m8n8.x4.shared.b16 {%0,%1,%2,%3}, [%4];"
                 : "=r"(r0), "=r"(r1), "=r"(r2), "=r"(r3) : "r"(addr));
}
__device__ __forceinline__ void mma_bf16(float* c, const uint32_t* a,
                                         uint32_t b0, uint32_t b1) {
    asm volatile(
        "mma.sync.aligned.m16n8k16.row.col.f32.bf16.bf16.f32 "
        "{%0,%1,%2,%3}, {%4,%5,%6,%7}, {%8,%9}, {%0,%1,%2,%3};"
        : "+f"(c[0]), "+f"(c[1]), "+f"(c[2]), "+f"(c[3])
        : "r"(a[0]), "r"(a[1]), "r"(a[2]), "r"(a[3]), "r"(b0), "r"(b1));
}
__device__ __forceinline__ uint32_t smem_u32(const void* p) {
    uint32_t a;
    asm("{ .reg .u64 t; cvta.to.shared.u64 t, %1; cvt.u32.u64 %0, t; }"
        : "=r"(a) : "l"(p));
    return a;
}
__device__ __forceinline__ void cp_async16(uint32_t dst, const void* src, bool pred) {
    int sz = pred ? 16 : 0;
    asm volatile("cp.async.cg.shared.global [%0], [%1], 16, %2;"
                 :: "r"(dst), "l"(src), "r"(sz) : "memory");
}
#define CP_COMMIT() asm volatile("cp.async.commit_group;" ::: "memory")
#define CP_WAIT(N)  asm volatile("cp.async.wait_group %0;" :: "n"(N) : "memory")

// ---------------------------------------------------------------------------
// Conv: 2-D tiled implicit GEMM, fully-unrolled pipelined inner loop.
// Tile = 16x16 px x 64 co; halo 18x18x64ci SW128.
// R14: 256 threads / 8 warps, warp tile 64px x 32co.
//   LDS/MAC = 2(64+32)/(64*32) = 0.094 B/MAC -> crossbar demand 103 B/cyc
//   < 128 limit, so the tensor pipe becomes the sole limiter (R13's 32x32
//   tile needed 137 B/cyc -> crossbar-bound at ~50%).
//   acc 64 regs fits: 256 thr -> 256-reg cap (R9's failure was at 512 thr).
// SMEM: B 73728 | A0 41472 | A1 41472 = 156672 bytes.
// ---------------------------------------------------------------------------
#define NT_TILES  1568
#define HALO      18
#define APOS      (HALO*HALO)        // 324
#define A_OPS     (APOS*8)           // 2592
#define SMEM_B    0u
#define SMEM_A0   73728u
#define SMEM_A1   115200u
#define CONV_SMEM 156672u

__global__ __launch_bounds__(256, 1)
void conv_mma_kernel(const __nv_bfloat16* __restrict__ xt,
                     const __nv_bfloat16* __restrict__ wk,
                     const float* __restrict__ bias,
                     float* __restrict__ out) {
    extern __shared__ char smem[];
    const uint32_t sb = smem_u32(smem);

    const int tid  = threadIdx.x;
    const int wid  = tid >> 5;         // 0..7
    const int lane = tid & 31;
    const int wm   = wid & 3;          // 64-px group (4 groups)
    const int wc   = wid >> 2;         // co half (32 co)
    const int lrow = lane & 15;
    const int lcol = (lane >> 4) << 4;
    const int g8   = lane >> 2;
    const int tg   = lane & 3;

    // Bias for the 8 co columns this thread owns
    float bv[4][2];
    #pragma unroll
    for (int nf = 0; nf < 4; ++nf) {
        int cob = wc * 32 + nf * 8 + tg * 2;
        bv[nf][0] = bias[cob];
        bv[nf][1] = bias[cob + 1];
    }

    // Stage all 9 weight tiles (SW128 K-major: row=co, 128B of ci)
    for (int idx = tid; idx < 9 * 64 * 8; idx += 256) {
        int c  = idx & 7;
        int co = (idx >> 3) & 63;
        int k  = idx >> 9;
        uint4 v = *(const uint4*)(wk + ((k * 64 + co) * 64) + c * 8);
        *(uint4*)(smem + SMEM_B + k * 8192 + SW128((uint32_t)(co * 128 + c * 16))) = v;
    }

    // Per-lane fixed pieces: pixel p = wm*64 + mf*16 + lrow, mf = 0..3
    int browA[4];
    #pragma unroll
    for (int mf = 0; mf < 4; ++mf) {
        int p = wm * 64 + mf * 16 + lrow;
        browA[mf] = ((p >> 4) + 1) * HALO + (p & 15) + 1;
    }
    // B: row = wc*32 + j*16 + lrow; (row&7) == (lrow&7). Kernel-invariant
    // bases with the bit-4 part of the swizzle folded in:
    const uint32_t bXor = (uint32_t)((lrow & 7) << 4);
    const uint32_t XB   = bXor & 0x60;
    uint32_t BB[2];
    #pragma unroll
    for (int j = 0; j < 2; ++j)
        BB[j] = sb + SMEM_B + (uint32_t)((wc * 32 + j * 16 + lrow) * 128)
                + ((uint32_t)lcol ^ (bXor & 0x10));

    // Stage one tile's 18x18 halo via cp.async (zfill OOB)
    auto stage = [&](int t, uint32_t aoff) {
        const int img = t / 49;
        const int rem = t - img * 49;
        const int oh0 = (rem / 7) * 16;
        const int ow0 = (rem - (rem / 7) * 7) * 16;
        const __nv_bfloat16* base = xt + (size_t)img * PIX * 64;
        #pragma unroll
        for (int it = 0; it < 11; ++it) {
            int idx = it * 256 + tid;
            if (idx < A_OPS) {
                int c   = idx & 7;
                int pos = idx >> 3;
                int r   = pos / HALO;
                int w   = pos - r * HALO;
                int ih  = oh0 - 1 + r;
                int iw  = ow0 - 1 + w;
                bool ok = ((unsigned)ih < (unsigned)HH) &
                          ((unsigned)iw < (unsigned)WW);
                const void* src = ok ? (const void*)(base + ((size_t)ih * WW + iw) * 64 + c * 8)
                                     : (const void*)base;
                cp_async16(sb + aoff + SW128((uint32_t)(pos * 128 + c * 16)), src, ok);
            }
        }
        CP_COMMIT();
    };

    int t = blockIdx.x;
    if (t < NT_TILES) stage(t, SMEM_A0);
    int pb = 0;

    for (; t < NT_TILES; t += gridDim.x, pb ^= 1) {
        const int img = t / 49;
        const int rem = t - img * 49;
        const int oh0 = (rem / 7) * 16;
        const int ow0 = (rem - (rem / 7) * 7) * 16;
        const uint32_t ab = sb + (pb ? SMEM_A1 : SMEM_A0);

        const int tn = t + gridDim.x;
        if (tn < NT_TILES) {
            stage(tn, pb ? SMEM_A0 : SMEM_A1);
            CP_WAIT(1);
        } else {
            CP_WAIT(0);
        }
        __syncthreads();

        float acc[4][4][4];
        #pragma unroll
        for (int mf = 0; mf < 4; ++mf)
            #pragma unroll
            for (int nf = 0; nf < 4; ++nf)
                #pragma unroll
                for (int j = 0; j < 4; ++j) acc[mf][nf][j] = 0.f;

        // ---- fully-unrolled pipelined 36-chunk stream ----
        uint32_t aF[2][4][4], bF[2][2][4];
        uint32_t CA[4], XA[4];

#define TAP_SHIFT(T) (((T) / 3 - 1) * HALO + ((T) % 3 - 1))

#define SETUP_TAP(T) do {                                                     \
    _Pragma("unroll")                                                         \
    for (int mf = 0; mf < 4; ++mf) {                                          \
        int row = browA[mf] + (TAP_SHIFT(T));                                 \
        uint32_t xa = (uint32_t)((row & 7) << 4);                             \
        XA[mf] = xa & 0x60;                                                   \
        CA[mf] = ab + (uint32_t)(row * 128) + ((uint32_t)lcol ^ (xa & 0x10)); \
    }                                                                         \
} while (0)

#define LOAD_CHUNK(Q, BUF) do {                                               \
    const int _s = (Q) & 3;                                                   \
    _Pragma("unroll")                                                         \
    for (int mf = 0; mf < 4; ++mf) {                                          \
        uint32_t ad = CA[mf] + ((uint32_t)(_s * 32) ^ XA[mf]);                \
        ldsm_x4(aF[BUF][mf][0], aF[BUF][mf][1], aF[BUF][mf][2],               \
                aF[BUF][mf][3], ad);                                          \
    }                                                                         \
    _Pragma("unroll")                                                         \
    for (int j = 0; j < 2; ++j) {                                             \
        uint32_t bd = BB[j] + (uint32_t)(((Q) >> 2) * 8192)                   \
                      + ((uint32_t)(_s * 32) ^ XB);                           \
        ldsm_x4(bF[BUF][j][0], bF[BUF][j][1], bF[BUF][j][2],                  \
                bF[BUF][j][3], bd);                                           \
    }                                                                         \
} while (0)

#define MMA_CHUNK(BUF) do {                                                   \
    _Pragma("unroll")                                                         \
    for (int mf = 0; mf < 4; ++mf)                                            \
        _Pragma("unroll")                                                     \
        for (int j = 0; j < 2; ++j) {                                         \
            mma_bf16(acc[mf][2 * j],     aF[BUF][mf],                         \
                     bF[BUF][j][0], bF[BUF][j][2]);                           \
            mma_bf16(acc[mf][2 * j + 1], aF[BUF][mf],                         \
                     bF[BUF][j][1], bF[BUF][j][3]);                           \
        }                                                                     \
} while (0)

        SETUP_TAP(0);
        LOAD_CHUNK(0, 0);
        #pragma unroll
        for (int q = 0; q < 36; ++q) {
            const int qn = q + 1;
            if (qn < 36) {
                if ((qn & 3) == 0) SETUP_TAP(qn >> 2);
                LOAD_CHUNK(qn, qn & 1);
            }
            MMA_CHUNK(q & 1);
        }
#undef TAP_SHIFT
#undef SETUP_TAP
#undef LOAD_CHUNK
#undef MMA_CHUNK

        __syncthreads();   // buf pb reads done before restage

        // Epilogue: r = wm*4+mf, w = g8 / g8+8
        #pragma unroll
        for (int mf = 0; mf < 4; ++mf) {
            const int r = wm * 4 + mf;
            float* orow = out + (size_t)img * 64 * PIX +
                          (size_t)(oh0 + r) * WW + ow0;
            #pragma unroll
            for (int nf = 0; nf < 4; ++nf) {
                const int cob = wc * 32 + nf * 8 + tg * 2;
                float* r0 = orow + (size_t)cob * PIX;
                float* r1 = orow + (size_t)(cob + 1) * PIX;
                r0[g8]     = acc[mf][nf][0] + bv[nf][0];
                r1[g8]     = acc[mf][nf][1] + bv[nf][1];
                r0[g8 + 8] = acc[mf][nf][2] + bv[nf][0];
                r1[g8 + 8] = acc[mf][nf][3] + bv[nf][1];
            }
        }
    }
}

// ---------------------------------------------------------------------------
extern "C" void kernel_launch(void* const* d_in, const int* in_sizes, int n_in,
                              void* d_out, int out_size) {
    const float* x    = (const float*)d_in[0];
    const float* w    = (const float*)d_in[1];
    const float* bias = (const float*)d_in[2];
    float* out        = (float*)d_out;

    void *pxt, *pwk, *psc;
    cudaGetSymbolAddress(&pxt, g_xt);
    cudaGetSymbolAddress(&pwk, g_wk);
    cudaGetSymbolAddress(&psc, g_scale);
    __nv_bfloat16* xt = (__nv_bfloat16*)pxt;
    __nv_bfloat16* wk = (__nv_bfloat16*)pwk;
    float2* scale     = (float2*)psc;

    const int n4x = NX / 4;

    // Launch order keeps conv at the ncu capture slot (#4).
    wquant_repack_kernel<<<4, 256>>>((const float4*)w, wk);
    bfp_scale_kernel<<<(n4x + 2303) / 2304, 256>>>((const float4*)x, n4x,
                                                   NGROUPS, scale);
    quant_transpose_kernel<<<dim3(PIX / 64, N_BATCH), 256>>>((const float4*)x,
                                                             scale, xt);
    cudaFuncSetAttribute(conv_mma_kernel,
                         cudaFuncAttributeMaxDynamicSharedMemorySize,
                         CONV_SMEM);
    conv_mma_kernel<<<148, 256, CONV_SMEM>>>(xt, wk, bias, out);
}

// round 15
// speedup vs baseline: 1.1903x; 1.1903x over previous
#include <cuda_runtime.h>
#include <cuda_bf16.h>
#include <cstdint>

// ---------------------------------------------------------------------------
// Problem shape
// ---------------------------------------------------------------------------
#define N_BATCH 32
#define CH      64
#define HH      112
#define WW      112
#define PIX     (HH*WW)              // 12544
#define NX      (N_BATCH*CH*PIX)     // 25,690,112
#define N4      (NX/4)               // 6,422,528 float4s
#define NWELEM  (64*64*3*3)          // 36,864

__device__ __align__(16) __nv_bfloat16 g_xt[NX];       // quantized x, NHWC
__device__ __align__(16) __nv_bfloat16 g_wk[9*64*64];  // [k][co][ci]

#define SW128(off) ((off) ^ (((off) >> 3) & 0x70))

// ---------------------------------------------------------------------------
// Weights: fused BFP quantize + repack OIHW -> [k][co][ci]. 4 blocks.
// ---------------------------------------------------------------------------
__global__ __launch_bounds__(256)
void wquant_repack_kernel(const float4* __restrict__ src,
                          __nv_bfloat16* __restrict__ wk) {
    __shared__ float sMax[2304];
    __shared__ float sScl[256];
    __shared__ float sInv[256];
    const int tid = threadIdx.x;
    const int n4  = NWELEM / 4;      // 9216
    const long base = (long)blockIdx.x * 2304;

    float4 v[9];
    #pragma unroll
    for (int r = 0; r < 9; ++r) {
        long j = base + r * 256 + tid;
        float4 x = make_float4(0.f, 0.f, 0.f, 0.f);
        if (j < n4) x = src[j];
        v[r] = x;
        sMax[r * 256 + tid] =
            fmaxf(fmaxf(fabsf(x.x), fabsf(x.y)), fmaxf(fabsf(x.z), fabsf(x.w)));
    }
    __syncthreads();
    {
        float m = sMax[tid * 9];
        #pragma unroll
        for (int i = 1; i < 9; ++i) m = fmaxf(m, sMax[tid * 9 + i]);
        float scl = 0.f, inv = 0.f;
        if (m > 0.f) {
            float e = floorf(log2f(m));
            scl = exp2f(e - 7.f);
            inv = exp2f(7.f - e);
        }
        sScl[tid] = scl;
        sInv[tid] = inv;
    }
    __syncthreads();
    #pragma unroll
    for (int r = 0; r < 9; ++r) {
        long j = base + r * 256 + tid;
        if (j >= n4) continue;
        int g = (r * 256 + tid) / 9;
        float scl = sScl[g], inv = sInv[g];
        float q[4];
        q[0] = rintf(v[r].x * inv) * scl;
        q[1] = rintf(v[r].y * inv) * scl;
        q[2] = rintf(v[r].z * inv) * scl;
        q[3] = rintf(v[r].w * inv) * scl;
        #pragma unroll
        for (int e = 0; e < 4; ++e) {
            long f  = j * 4 + e;             // flat OIHW index
            int co  = (int)(f / 576);
            int rem = (int)(f - (long)co * 576);
            int ci  = rem / 9;
            int k   = rem - ci * 9;
            wk[k * 4096 + co * 64 + ci] = __float2bfloat16_rn(q[e]);
        }
    }
}

// ---------------------------------------------------------------------------
// x path, FUSED: group-scale + quantize + NCHW->NHWC transpose, one pass.
// Block = [64 ci rows x 256 px] of one image (grid 49 x 32).
// Per ci row: own f4 range [r0, r0+64); groups (36 flat = 9 f4) covering it
// lie within flat f4 range [r0-8, r0+72) (flat-contiguous across row ends).
// Phase1: own f4 -> registers + absmax -> sM[row][8..72); halo absmax ->
//         sM[row][0..8) and [72..80) (clamped at tensor ends).
// Phase2: 8 group slots per row: scl/inv from 9-f4 max.
// Phase3: quantize registers -> sT[ci][px] (odd stride).
// Phase4: transposed uint4 stores to NHWC.
// Dynamic smem: sM 64x81 f32 | sScl 512 | sInv 512 | sT 64x257 bf16.
// ---------------------------------------------------------------------------
#define QT_SM_OFF   0u
#define QT_SCL_OFF  20736u
#define QT_INV_OFF  22784u
#define QT_ST_OFF   24832u
#define QT_SMEM     (24832u + 64u*257u*2u)   // 57728 bytes

__global__ __launch_bounds__(256)
void fused_qt_kernel(const float4* __restrict__ x,
                     __nv_bfloat16* __restrict__ dst) {
    extern __shared__ char qsm[];
    float*         sM   = (float*)(qsm + QT_SM_OFF);    // [64][81]
    float*         sScl = (float*)(qsm + QT_SCL_OFF);   // [64][8]
    float*         sInv = (float*)(qsm + QT_INV_OFF);   // [64][8]
    __nv_bfloat16* sT   = (__nv_bfloat16*)(qsm + QT_ST_OFF); // [64][257]

    const int tid = threadIdx.x;
    const int n   = blockIdx.y;
    const int p0  = blockIdx.x * 256;
    const int f0  = (p0 >> 2);

    // Phase 1a: own 16 float4 per thread -> registers, absmax -> sM
    float4 v[16];
    #pragma unroll
    for (int it = 0; it < 16; ++it) {
        int idx = it * 256 + tid;          // [0,4096)
        int row = idx >> 6;
        int c   = idx & 63;
        int r0  = (n * 64 + row) * 3136 + f0;
        float4 a = x[r0 + c];
        v[it] = a;
        sM[row * 81 + 8 + c] =
            fmaxf(fmaxf(fabsf(a.x), fabsf(a.y)), fmaxf(fabsf(a.z), fabsf(a.w)));
    }
    // Phase 1b: halo 8 f4 each side per row (flat-contiguous; clamp at ends)
    #pragma unroll
    for (int it = 0; it < 4; ++it) {
        int idx = it * 256 + tid;          // [0,1024)
        int row = idx >> 4;
        int h   = idx & 15;
        int pos = (h < 8) ? h : (h + 64);  // [0,8) or [72,80)
        int r0  = (n * 64 + row) * 3136 + f0;
        long f4 = (long)r0 - 8 + pos;
        float am = 0.f;
        if (f4 >= 0 && f4 < N4) {
            float4 a = x[f4];
            am = fmaxf(fmaxf(fabsf(a.x), fabsf(a.y)),
                       fmaxf(fabsf(a.z), fabsf(a.w)));
        }
        sM[row * 81 + pos] = am;
    }
    __syncthreads();

    // Phase 2: per-row group scales (8 slots per row = 512 total)
    #pragma unroll
    for (int it = 0; it < 2; ++it) {
        int idx = it * 256 + tid;          // [0,512)
        int row = idx >> 3;
        int s   = idx & 7;
        int r0  = (n * 64 + row) * 3136 + f0;
        int g   = r0 / 9 + s;
        int pos = 9 * g - r0 + 8;          // in [0,72)
        float m = sM[row * 81 + pos];
        #pragma unroll
        for (int i = 1; i < 9; ++i) m = fmaxf(m, sM[row * 81 + pos + i]);
        float scl = 0.f, inv = 0.f;
        if (m > 0.f) {
            float e = floorf(log2f(m));
            scl = exp2f(e - 7.f);          // exact powers of two
            inv = exp2f(7.f - e);
        }
        sScl[row * 8 + s] = scl;
        sInv[row * 8 + s] = inv;
    }
    __syncthreads();

    // Phase 3: quantize registers -> sT[ci][px]
    #pragma unroll
    for (int it = 0; it < 16; ++it) {
        int idx = it * 256 + tid;
        int row = idx >> 6;
        int c   = idx & 63;
        int r0  = (n * 64 + row) * 3136 + f0;
        int s   = ((r0 % 9) + c) / 9;      // slot = (r0+c)/9 - r0/9
        float scl = sScl[row * 8 + s];
        float inv = sInv[row * 8 + s];
        float4 a = v[it];
        __nv_bfloat16* sp = &sT[row * 257 + c * 4];
        sp[0] = __float2bfloat16_rn(rintf(a.x * inv) * scl);
        sp[1] = __float2bfloat16_rn(rintf(a.y * inv) * scl);
        sp[2] = __float2bfloat16_rn(rintf(a.z * inv) * scl);
        sp[3] = __float2bfloat16_rn(rintf(a.w * inv) * scl);
    }
    __syncthreads();

    // Phase 4: transposed uint4 stores (8 ci per store)
    #pragma unroll
    for (int it = 0; it < 8; ++it) {
        int idx = it * 256 + tid;          // [0,2048)
        int px  = idx >> 3;
        int c   = idx & 7;
        uint4 o;
        __nv_bfloat16* e = (__nv_bfloat16*)&o;
        #pragma unroll
        for (int j = 0; j < 8; ++j) e[j] = sT[(c * 8 + j) * 257 + px];
        *(uint4*)(dst + ((size_t)(n * PIX + p0 + px)) * 64 + c * 8) = o;
    }
}

// ---------------------------------------------------------------------------
// mma.sync / cp.async helpers
// ---------------------------------------------------------------------------
__device__ __forceinline__ void ldsm_x4(uint32_t& r0, uint32_t& r1,
                                        uint32_t& r2, uint32_t& r3,
                                        uint32_t addr) {
    asm volatile("ldmatrix.sync.aligned.m8n8.x4.shared.b16 {%0,%1,%2,%3}, [%4];"
                 : "=r"(r0), "=r"(r1), "=r"(r2), "=r"(r3) : "r"(addr));
}
__device__ __forceinline__ void mma_bf16(float* c, const uint32_t* a,
                                         uint32_t b0, uint32_t b1) {
    asm volatile(
        "mma.sync.aligned.m16n8k16.row.col.f32.bf16.bf16.f32 "
        "{%0,%1,%2,%3}, {%4,%5,%6,%7}, {%8,%9}, {%0,%1,%2,%3};"
        : "+f"(c[0]), "+f"(c[1]), "+f"(c[2]), "+f"(c[3])
        : "r"(a[0]), "r"(a[1]), "r"(a[2]), "r"(a[3]), "r"(b0), "r"(b1));
}
__device__ __forceinline__ uint32_t smem_u32(const void* p) {
    uint32_t a;
    asm("{ .reg .u64 t; cvta.to.shared.u64 t, %1; cvt.u32.u64 %0, t; }"
        : "=r"(a) : "l"(p));
    return a;
}
__device__ __forceinline__ void cp_async16(uint32_t dst, const void* src, bool pred) {
    int sz = pred ? 16 : 0;
    asm volatile("cp.async.cg.shared.global [%0], [%1], 16, %2;"
                 :: "r"(dst), "l"(src), "r"(sz) : "memory");
}
#define CP_COMMIT() asm volatile("cp.async.commit_group;" ::: "memory")
#define CP_WAIT(N)  asm volatile("cp.async.wait_group %0;" :: "n"(N) : "memory")

// ---------------------------------------------------------------------------
// Conv: R13 configuration (best measured: 94.3us).
// 2-D tiled implicit GEMM, fully-unrolled pipelined inner loop.
// Tile = 16x16 px x 64 co; halo 18x18x64ci SW128; 512 thr / 16 warps,
// warp tile 32px x 32co. (R14's 64x32 tile spilled: regs=255 -> reverted.)
// SMEM: B 73728 | A0 41472 | A1 41472 = 156672 bytes.
// ---------------------------------------------------------------------------
#define NT_TILES  1568
#define HALO      18
#define APOS      (HALO*HALO)        // 324
#define A_OPS     (APOS*8)           // 2592
#define SMEM_B    0u
#define SMEM_A0   73728u
#define SMEM_A1   115200u
#define CONV_SMEM 156672u

__global__ __launch_bounds__(512, 1)
void conv_mma_kernel(const __nv_bfloat16* __restrict__ xt,
                     const __nv_bfloat16* __restrict__ wk,
                     const float* __restrict__ bias,
                     float* __restrict__ out) {
    extern __shared__ char smem[];
    const uint32_t sb = smem_u32(smem);

    const int tid  = threadIdx.x;
    const int wid  = tid >> 5;         // 0..15
    const int lane = tid & 31;
    const int wm   = wid & 7;          // 32-px group
    const int wc   = wid >> 3;         // co half (32 co)
    const int lrow = lane & 15;
    const int lcol = (lane >> 4) << 4;
    const int g8   = lane >> 2;
    const int tg   = lane & 3;

    float bv[4][2];
    #pragma unroll
    for (int nf = 0; nf < 4; ++nf) {
        int cob = wc * 32 + nf * 8 + tg * 2;
        bv[nf][0] = bias[cob];
        bv[nf][1] = bias[cob + 1];
    }

    for (int idx = tid; idx < 9 * 64 * 8; idx += 512) {
        int c  = idx & 7;
        int co = (idx >> 3) & 63;
        int k  = idx >> 9;
        uint4 v = *(const uint4*)(wk + ((k * 64 + co) * 64) + c * 8);
        *(uint4*)(smem + SMEM_B + k * 8192 + SW128((uint32_t)(co * 128 + c * 16))) = v;
    }

    int browA[2];
    #pragma unroll
    for (int mf = 0; mf < 2; ++mf) {
        int p = wm * 32 + mf * 16 + lrow;
        browA[mf] = ((p >> 4) + 1) * HALO + (p & 15) + 1;
    }
    const uint32_t bXor = (uint32_t)((lrow & 7) << 4);
    const uint32_t XB   = bXor & 0x60;
    uint32_t BB[2];
    #pragma unroll
    for (int j = 0; j < 2; ++j)
        BB[j] = sb + SMEM_B + (uint32_t)((wc * 32 + j * 16 + lrow) * 128)
                + ((uint32_t)lcol ^ (bXor & 0x10));

    auto stage = [&](int t, uint32_t aoff) {
        const int img = t / 49;
        const int rem = t - img * 49;
        const int oh0 = (rem / 7) * 16;
        const int ow0 = (rem - (rem / 7) * 7) * 16;
        const __nv_bfloat16* base = xt + (size_t)img * PIX * 64;
        #pragma unroll
        for (int it = 0; it < 6; ++it) {
            int idx = it * 512 + tid;
            if (idx < A_OPS) {
                int c   = idx & 7;
                int pos = idx >> 3;
                int r   = pos / HALO;
                int w   = pos - r * HALO;
                int ih  = oh0 - 1 + r;
                int iw  = ow0 - 1 + w;
                bool ok = ((unsigned)ih < (unsigned)HH) &
                          ((unsigned)iw < (unsigned)WW);
                const void* src = ok ? (const void*)(base + ((size_t)ih * WW + iw) * 64 + c * 8)
                                     : (const void*)base;
                cp_async16(sb + aoff + SW128((uint32_t)(pos * 128 + c * 16)), src, ok);
            }
        }
        CP_COMMIT();
    };

    int t = blockIdx.x;
    if (t < NT_TILES) stage(t, SMEM_A0);
    int pb = 0;

    for (; t < NT_TILES; t += gridDim.x, pb ^= 1) {
        const int img = t / 49;
        const int rem = t - img * 49;
        const int oh0 = (rem / 7) * 16;
        const int ow0 = (rem - (rem / 7) * 7) * 16;
        const uint32_t ab = sb + (pb ? SMEM_A1 : SMEM_A0);

        const int tn = t + gridDim.x;
        if (tn < NT_TILES) {
            stage(tn, pb ? SMEM_A0 : SMEM_A1);
            CP_WAIT(1);
        } else {
            CP_WAIT(0);
        }
        __syncthreads();

        float acc[2][4][4];
        #pragma unroll
        for (int mf = 0; mf < 2; ++mf)
            #pragma unroll
            for (int nf = 0; nf < 4; ++nf)
                #pragma unroll
                for (int j = 0; j < 4; ++j) acc[mf][nf][j] = 0.f;

        uint32_t aF[2][2][4], bF[2][2][4];
        uint32_t CA[2], XA[2];

#define TAP_SHIFT(T) (((T) / 3 - 1) * HALO + ((T) % 3 - 1))

#define SETUP_TAP(T) do {                                                     \
    _Pragma("unroll")                                                         \
    for (int mf = 0; mf < 2; ++mf) {                                          \
        int row = browA[mf] + (TAP_SHIFT(T));                                 \
        uint32_t xa = (uint32_t)((row & 7) << 4);                             \
        XA[mf] = xa & 0x60;                                                   \
        CA[mf] = ab + (uint32_t)(row * 128) + ((uint32_t)lcol ^ (xa & 0x10)); \
    }                                                                         \
} while (0)

#define LOAD_CHUNK(Q, BUF) do {                                               \
    const int _s = (Q) & 3;                                                   \
    _Pragma("unroll")                                                         \
    for (int mf = 0; mf < 2; ++mf) {                                          \
        uint32_t ad = CA[mf] + ((uint32_t)(_s * 32) ^ XA[mf]);                \
        ldsm_x4(aF[BUF][mf][0], aF[BUF][mf][1], aF[BUF][mf][2],               \
                aF[BUF][mf][3], ad);                                          \
    }                                                                         \
    _Pragma("unroll")                                                         \
    for (int j = 0; j < 2; ++j) {                                             \
        uint32_t bd = BB[j] + (uint32_t)(((Q) >> 2) * 8192)                   \
                      + ((uint32_t)(_s * 32) ^ XB);                           \
        ldsm_x4(bF[BUF][j][0], bF[BUF][j][1], bF[BUF][j][2],                  \
                bF[BUF][j][3], bd);                                           \
    }                                                                         \
} while (0)

#define MMA_CHUNK(BUF) do {                                                   \
    _Pragma("unroll")                                                         \
    for (int mf = 0; mf < 2; ++mf)                                            \
        _Pragma("unroll")                                                     \
        for (int j = 0; j < 2; ++j) {                                         \
            mma_bf16(acc[mf][2 * j],     aF[BUF][mf],                         \
                     bF[BUF][j][0], bF[BUF][j][2]);                           \
            mma_bf16(acc[mf][2 * j + 1], aF[BUF][mf],                         \
                     bF[BUF][j][1], bF[BUF][j][3]);                           \
        }                                                                     \
} while (0)

        SETUP_TAP(0);
        LOAD_CHUNK(0, 0);
        #pragma unroll
        for (int q = 0; q < 36; ++q) {
            const int qn = q + 1;
            if (qn < 36) {
                if ((qn & 3) == 0) SETUP_TAP(qn >> 2);
                LOAD_CHUNK(qn, qn & 1);
            }
            MMA_CHUNK(q & 1);
        }
#undef TAP_SHIFT
#undef SETUP_TAP
#undef LOAD_CHUNK
#undef MMA_CHUNK

        __syncthreads();

        #pragma unroll
        for (int mf = 0; mf < 2; ++mf) {
            const int r = wm * 2 + mf;
            float* orow = out + (size_t)img * 64 * PIX +
                          (size_t)(oh0 + r) * WW + ow0;
            #pragma unroll
            for (int nf = 0; nf < 4; ++nf) {
                const int cob = wc * 32 + nf * 8 + tg * 2;
                float* r0 = orow + (size_t)cob * PIX;
                float* r1 = orow + (size_t)(cob + 1) * PIX;
                r0[g8]     = acc[mf][nf][0] + bv[nf][0];
                r1[g8]     = acc[mf][nf][1] + bv[nf][1];
                r0[g8 + 8] = acc[mf][nf][2] + bv[nf][0];
                r1[g8 + 8] = acc[mf][nf][3] + bv[nf][1];
            }
        }
    }
}

// ---------------------------------------------------------------------------
extern "C" void kernel_launch(void* const* d_in, const int* in_sizes, int n_in,
                              void* d_out, int out_size) {
    const float* x    = (const float*)d_in[0];
    const float* w    = (const float*)d_in[1];
    const float* bias = (const float*)d_in[2];
    float* out        = (float*)d_out;

    void *pxt, *pwk;
    cudaGetSymbolAddress(&pxt, g_xt);
    cudaGetSymbolAddress(&pwk, g_wk);
    __nv_bfloat16* xt = (__nv_bfloat16*)pxt;
    __nv_bfloat16* wk = (__nv_bfloat16*)pwk;

    wquant_repack_kernel<<<4, 256>>>((const float4*)w, wk);

    cudaFuncSetAttribute(fused_qt_kernel,
                         cudaFuncAttributeMaxDynamicSharedMemorySize,
                         QT_SMEM);
    fused_qt_kernel<<<dim3(PIX / 256, N_BATCH), 256, QT_SMEM>>>(
        (const float4*)x, xt);

    cudaFuncSetAttribute(conv_mma_kernel,
                         cudaFuncAttributeMaxDynamicSharedMemorySize,
                         CONV_SMEM);
    conv_mma_kernel<<<148, 512, CONV_SMEM>>>(xt, wk, bias, out);
}

// round 16
// speedup vs baseline: 1.2303x; 1.0336x over previous
#include <cuda_runtime.h>
#include <cuda_bf16.h>
#include <cstdint>

// ---------------------------------------------------------------------------
// Problem shape
// ---------------------------------------------------------------------------
#define N_BATCH 32
#define CH      64
#define HH      112
#define WW      112
#define PIX     (HH*WW)              // 12544
#define NX      (N_BATCH*CH*PIX)     // 25,690,112
#define N4      (NX/4)               // 6,422,528 float4s
#define NWELEM  (64*64*3*3)          // 36,864
#define X_BLOCKS 1568                // 49 x 32

__device__ __align__(16) __nv_bfloat16 g_xt[NX];       // quantized x, NHWC
__device__ __align__(16) __nv_bfloat16 g_wk[9*64*64];  // [k][co][ci]

#define SW128(off) ((off) ^ (((off) >> 3) & 0x70))

// ---------------------------------------------------------------------------
// FUSED preprocessing kernel.
// Blocks [0, 1568): x path — group-scale + quantize + NCHW->NHWC transpose.
// Blocks [1568, 1572): weight path — BFP quantize + repack OIHW->[k][co][ci].
// The 4 weight blocks ride along on idle SM capacity (was a serialized
// 7.6us launch in R15).
// ---------------------------------------------------------------------------
#define QT_SM_OFF   0u
#define QT_SCL_OFF  20736u
#define QT_INV_OFF  22784u
#define QT_ST_OFF   24832u
#define QT_SMEM     (24832u + 64u*257u*2u)   // 57728 bytes

__global__ __launch_bounds__(256)
void fused_pre_kernel(const float4* __restrict__ x,
                      const float4* __restrict__ w,
                      __nv_bfloat16* __restrict__ xt,
                      __nv_bfloat16* __restrict__ wk) {
    extern __shared__ char qsm[];
    const int tid = threadIdx.x;

    if (blockIdx.x >= X_BLOCKS) {
        // ---------------- weight path (4 blocks) ----------------
        float* sMax = (float*)qsm;              // 2304 floats
        float* sScl = (float*)qsm + 2304;       // 256
        float* sInv = (float*)qsm + 2560;       // 256
        const int n4  = NWELEM / 4;             // 9216
        const long base = (long)(blockIdx.x - X_BLOCKS) * 2304;

        float4 v[9];
        #pragma unroll
        for (int r = 0; r < 9; ++r) {
            long j = base + r * 256 + tid;
            float4 a = make_float4(0.f, 0.f, 0.f, 0.f);
            if (j < n4) a = w[j];
            v[r] = a;
            sMax[r * 256 + tid] =
                fmaxf(fmaxf(fabsf(a.x), fabsf(a.y)),
                      fmaxf(fabsf(a.z), fabsf(a.w)));
        }
        __syncthreads();
        {
            float m = sMax[tid * 9];
            #pragma unroll
            for (int i = 1; i < 9; ++i) m = fmaxf(m, sMax[tid * 9 + i]);
            float scl = 0.f, inv = 0.f;
            if (m > 0.f) {
                float e = floorf(log2f(m));
                scl = exp2f(e - 7.f);
                inv = exp2f(7.f - e);
            }
            sScl[tid] = scl;
            sInv[tid] = inv;
        }
        __syncthreads();
        #pragma unroll
        for (int r = 0; r < 9; ++r) {
            long j = base + r * 256 + tid;
            if (j >= n4) continue;
            int g = (r * 256 + tid) / 9;
            float scl = sScl[g], inv = sInv[g];
            float q[4];
            q[0] = rintf(v[r].x * inv) * scl;
            q[1] = rintf(v[r].y * inv) * scl;
            q[2] = rintf(v[r].z * inv) * scl;
            q[3] = rintf(v[r].w * inv) * scl;
            #pragma unroll
            for (int e = 0; e < 4; ++e) {
                long f  = j * 4 + e;             // flat OIHW index
                int co  = (int)(f / 576);
                int rem = (int)(f - (long)co * 576);
                int ci  = rem / 9;
                int k   = rem - ci * 9;
                wk[k * 4096 + co * 64 + ci] = __float2bfloat16_rn(q[e]);
            }
        }
        return;
    }

    // ---------------- x path (1568 blocks) ----------------
    float*         sM   = (float*)(qsm + QT_SM_OFF);    // [64][81]
    float*         sScl = (float*)(qsm + QT_SCL_OFF);   // [64][8]
    float*         sInv = (float*)(qsm + QT_INV_OFF);   // [64][8]
    __nv_bfloat16* sT   = (__nv_bfloat16*)(qsm + QT_ST_OFF); // [64][257]

    const int n   = blockIdx.x / 49;
    const int p0  = (blockIdx.x - n * 49) * 256;
    const int f0  = (p0 >> 2);

    // Phase 1a: own 16 float4 per thread -> registers, absmax -> sM
    float4 v[16];
    #pragma unroll
    for (int it = 0; it < 16; ++it) {
        int idx = it * 256 + tid;          // [0,4096)
        int row = idx >> 6;
        int c   = idx & 63;
        int r0  = (n * 64 + row) * 3136 + f0;
        float4 a = x[r0 + c];
        v[it] = a;
        sM[row * 81 + 8 + c] =
            fmaxf(fmaxf(fabsf(a.x), fabsf(a.y)), fmaxf(fabsf(a.z), fabsf(a.w)));
    }
    // Phase 1b: halo 8 f4 each side per row (flat-contiguous; clamp at ends)
    #pragma unroll
    for (int it = 0; it < 4; ++it) {
        int idx = it * 256 + tid;          // [0,1024)
        int row = idx >> 4;
        int h   = idx & 15;
        int pos = (h < 8) ? h : (h + 64);  // [0,8) or [72,80)
        int r0  = (n * 64 + row) * 3136 + f0;
        long f4 = (long)r0 - 8 + pos;
        float am = 0.f;
        if (f4 >= 0 && f4 < N4) {
            float4 a = x[f4];
            am = fmaxf(fmaxf(fabsf(a.x), fabsf(a.y)),
                       fmaxf(fabsf(a.z), fabsf(a.w)));
        }
        sM[row * 81 + pos] = am;
    }
    __syncthreads();

    // Phase 2: per-row group scales (8 slots per row = 512 total)
    #pragma unroll
    for (int it = 0; it < 2; ++it) {
        int idx = it * 256 + tid;          // [0,512)
        int row = idx >> 3;
        int s   = idx & 7;
        int r0  = (n * 64 + row) * 3136 + f0;
        int g   = r0 / 9 + s;
        int pos = 9 * g - r0 + 8;          // in [0,72)
        float m = sM[row * 81 + pos];
        #pragma unroll
        for (int i = 1; i < 9; ++i) m = fmaxf(m, sM[row * 81 + pos + i]);
        float scl = 0.f, inv = 0.f;
        if (m > 0.f) {
            float e = floorf(log2f(m));
            scl = exp2f(e - 7.f);          // exact powers of two
            inv = exp2f(7.f - e);
        }
        sScl[row * 8 + s] = scl;
        sInv[row * 8 + s] = inv;
    }
    __syncthreads();

    // Phase 3: quantize registers -> sT[ci][px]
    #pragma unroll
    for (int it = 0; it < 16; ++it) {
        int idx = it * 256 + tid;
        int row = idx >> 6;
        int c   = idx & 63;
        int r0  = (n * 64 + row) * 3136 + f0;
        int s   = ((r0 % 9) + c) / 9;      // slot = (r0+c)/9 - r0/9
        float scl = sScl[row * 8 + s];
        float inv = sInv[row * 8 + s];
        float4 a = v[it];
        __nv_bfloat16* sp = &sT[row * 257 + c * 4];
        sp[0] = __float2bfloat16_rn(rintf(a.x * inv) * scl);
        sp[1] = __float2bfloat16_rn(rintf(a.y * inv) * scl);
        sp[2] = __float2bfloat16_rn(rintf(a.z * inv) * scl);
        sp[3] = __float2bfloat16_rn(rintf(a.w * inv) * scl);
    }
    __syncthreads();

    // Phase 4: transposed uint4 stores (8 ci per store)
    #pragma unroll
    for (int it = 0; it < 8; ++it) {
        int idx = it * 256 + tid;          // [0,2048)
        int px  = idx >> 3;
        int c   = idx & 7;
        uint4 o;
        __nv_bfloat16* e = (__nv_bfloat16*)&o;
        #pragma unroll
        for (int j = 0; j < 8; ++j) e[j] = sT[(c * 8 + j) * 257 + px];
        *(uint4*)(xt + ((size_t)(n * PIX + p0 + px)) * 64 + c * 8) = o;
    }
}

// ---------------------------------------------------------------------------
// mma.sync / cp.async helpers
// ---------------------------------------------------------------------------
__device__ __forceinline__ void ldsm_x4(uint32_t& r0, uint32_t& r1,
                                        uint32_t& r2, uint32_t& r3,
                                        uint32_t addr) {
    asm volatile("ldmatrix.sync.aligned.m8n8.x4.shared.b16 {%0,%1,%2,%3}, [%4];"
                 : "=r"(r0), "=r"(r1), "=r"(r2), "=r"(r3) : "r"(addr));
}
__device__ __forceinline__ void mma_bf16(float* c, const uint32_t* a,
                                         uint32_t b0, uint32_t b1) {
    asm volatile(
        "mma.sync.aligned.m16n8k16.row.col.f32.bf16.bf16.f32 "
        "{%0,%1,%2,%3}, {%4,%5,%6,%7}, {%8,%9}, {%0,%1,%2,%3};"
        : "+f"(c[0]), "+f"(c[1]), "+f"(c[2]), "+f"(c[3])
        : "r"(a[0]), "r"(a[1]), "r"(a[2]), "r"(a[3]), "r"(b0), "r"(b1));
}
__device__ __forceinline__ uint32_t smem_u32(const void* p) {
    uint32_t a;
    asm("{ .reg .u64 t; cvta.to.shared.u64 t, %1; cvt.u32.u64 %0, t; }"
        : "=r"(a) : "l"(p));
    return a;
}
__device__ __forceinline__ void cp_async16(uint32_t dst, const void* src, bool pred) {
    int sz = pred ? 16 : 0;
    asm volatile("cp.async.cg.shared.global [%0], [%1], 16, %2;"
                 :: "r"(dst), "l"(src), "r"(sz) : "memory");
}
#define CP_COMMIT() asm volatile("cp.async.commit_group;" ::: "memory")
#define CP_WAIT(N)  asm volatile("cp.async.wait_group %0;" :: "n"(N) : "memory")

// ---------------------------------------------------------------------------
// Conv: R13 configuration (best measured: 94.3us).
// 2-D tiled implicit GEMM, fully-unrolled pipelined inner loop.
// Tile = 16x16 px x 64 co; halo 18x18x64ci SW128; 512 thr / 16 warps,
// warp tile 32px x 32co.
// SMEM: B 73728 | A0 41472 | A1 41472 = 156672 bytes.
// ---------------------------------------------------------------------------
#define NT_TILES  1568
#define HALO      18
#define APOS      (HALO*HALO)        // 324
#define A_OPS     (APOS*8)           // 2592
#define SMEM_B    0u
#define SMEM_A0   73728u
#define SMEM_A1   115200u
#define CONV_SMEM 156672u

__global__ __launch_bounds__(512, 1)
void conv_mma_kernel(const __nv_bfloat16* __restrict__ xt,
                     const __nv_bfloat16* __restrict__ wk,
                     const float* __restrict__ bias,
                     float* __restrict__ out) {
    extern __shared__ char smem[];
    const uint32_t sb = smem_u32(smem);

    const int tid  = threadIdx.x;
    const int wid  = tid >> 5;         // 0..15
    const int lane = tid & 31;
    const int wm   = wid & 7;          // 32-px group
    const int wc   = wid >> 3;         // co half (32 co)
    const int lrow = lane & 15;
    const int lcol = (lane >> 4) << 4;
    const int g8   = lane >> 2;
    const int tg   = lane & 3;

    float bv[4][2];
    #pragma unroll
    for (int nf = 0; nf < 4; ++nf) {
        int cob = wc * 32 + nf * 8 + tg * 2;
        bv[nf][0] = bias[cob];
        bv[nf][1] = bias[cob + 1];
    }

    for (int idx = tid; idx < 9 * 64 * 8; idx += 512) {
        int c  = idx & 7;
        int co = (idx >> 3) & 63;
        int k  = idx >> 9;
        uint4 v = *(const uint4*)(wk + ((k * 64 + co) * 64) + c * 8);
        *(uint4*)(smem + SMEM_B + k * 8192 + SW128((uint32_t)(co * 128 + c * 16))) = v;
    }

    int browA[2];
    #pragma unroll
    for (int mf = 0; mf < 2; ++mf) {
        int p = wm * 32 + mf * 16 + lrow;
        browA[mf] = ((p >> 4) + 1) * HALO + (p & 15) + 1;
    }
    const uint32_t bXor = (uint32_t)((lrow & 7) << 4);
    const uint32_t XB   = bXor & 0x60;
    uint32_t BB[2];
    #pragma unroll
    for (int j = 0; j < 2; ++j)
        BB[j] = sb + SMEM_B + (uint32_t)((wc * 32 + j * 16 + lrow) * 128)
                + ((uint32_t)lcol ^ (bXor & 0x10));

    auto stage = [&](int t, uint32_t aoff) {
        const int img = t / 49;
        const int rem = t - img * 49;
        const int oh0 = (rem / 7) * 16;
        const int ow0 = (rem - (rem / 7) * 7) * 16;
        const __nv_bfloat16* base = xt + (size_t)img * PIX * 64;
        #pragma unroll
        for (int it = 0; it < 6; ++it) {
            int idx = it * 512 + tid;
            if (idx < A_OPS) {
                int c   = idx & 7;
                int pos = idx >> 3;
                int r   = pos / HALO;
                int w   = pos - r * HALO;
                int ih  = oh0 - 1 + r;
                int iw  = ow0 - 1 + w;
                bool ok = ((unsigned)ih < (unsigned)HH) &
                          ((unsigned)iw < (unsigned)WW);
                const void* src = ok ? (const void*)(base + ((size_t)ih * WW + iw) * 64 + c * 8)
                                     : (const void*)base;
                cp_async16(sb + aoff + SW128((uint32_t)(pos * 128 + c * 16)), src, ok);
            }
        }
        CP_COMMIT();
    };

    int t = blockIdx.x;
    if (t < NT_TILES) stage(t, SMEM_A0);
    int pb = 0;

    for (; t < NT_TILES; t += gridDim.x, pb ^= 1) {
        const int img = t / 49;
        const int rem = t - img * 49;
        const int oh0 = (rem / 7) * 16;
        const int ow0 = (rem - (rem / 7) * 7) * 16;
        const uint32_t ab = sb + (pb ? SMEM_A1 : SMEM_A0);

        const int tn = t + gridDim.x;
        if (tn < NT_TILES) {
            stage(tn, pb ? SMEM_A0 : SMEM_A1);
            CP_WAIT(1);
        } else {
            CP_WAIT(0);
        }
        __syncthreads();

        float acc[2][4][4];
        #pragma unroll
        for (int mf = 0; mf < 2; ++mf)
            #pragma unroll
            for (int nf = 0; nf < 4; ++nf)
                #pragma unroll
                for (int j = 0; j < 4; ++j) acc[mf][nf][j] = 0.f;

        uint32_t aF[2][2][4], bF[2][2][4];
        uint32_t CA[2], XA[2];

#define TAP_SHIFT(T) (((T) / 3 - 1) * HALO + ((T) % 3 - 1))

#define SETUP_TAP(T) do {                                                     \
    _Pragma("unroll")                                                         \
    for (int mf = 0; mf < 2; ++mf) {                                          \
        int row = browA[mf] + (TAP_SHIFT(T));                                 \
        uint32_t xa = (uint32_t)((row & 7) << 4);                             \
        XA[mf] = xa & 0x60;                                                   \
        CA[mf] = ab + (uint32_t)(row * 128) + ((uint32_t)lcol ^ (xa & 0x10)); \
    }                                                                         \
} while (0)

#define LOAD_CHUNK(Q, BUF) do {                                               \
    const int _s = (Q) & 3;                                                   \
    _Pragma("unroll")                                                         \
    for (int mf = 0; mf < 2; ++mf) {                                          \
        uint32_t ad = CA[mf] + ((uint32_t)(_s * 32) ^ XA[mf]);                \
        ldsm_x4(aF[BUF][mf][0], aF[BUF][mf][1], aF[BUF][mf][2],               \
                aF[BUF][mf][3], ad);                                          \
    }                                                                         \
    _Pragma("unroll")                                                         \
    for (int j = 0; j < 2; ++j) {                                             \
        uint32_t bd = BB[j] + (uint32_t)(((Q) >> 2) * 8192)                   \
                      + ((uint32_t)(_s * 32) ^ XB);                           \
        ldsm_x4(bF[BUF][j][0], bF[BUF][j][1], bF[BUF][j][2],                  \
                bF[BUF][j][3], bd);                                           \
    }                                                                         \
} while (0)

#define MMA_CHUNK(BUF) do {                                                   \
    _Pragma("unroll")                                                         \
    for (int mf = 0; mf < 2; ++mf)                                            \
        _Pragma("unroll")                                                     \
        for (int j = 0; j < 2; ++j) {                                         \
            mma_bf16(acc[mf][2 * j],     aF[BUF][mf],                         \
                     bF[BUF][j][0], bF[BUF][j][2]);                           \
            mma_bf16(acc[mf][2 * j + 1], aF[BUF][mf],                         \
                     bF[BUF][j][1], bF[BUF][j][3]);                           \
        }                                                                     \
} while (0)

        SETUP_TAP(0);
        LOAD_CHUNK(0, 0);
        #pragma unroll
        for (int q = 0; q < 36; ++q) {
            const int qn = q + 1;
            if (qn < 36) {
                if ((qn & 3) == 0) SETUP_TAP(qn >> 2);
                LOAD_CHUNK(qn, qn & 1);
            }
            MMA_CHUNK(q & 1);
        }
#undef TAP_SHIFT
#undef SETUP_TAP
#undef LOAD_CHUNK
#undef MMA_CHUNK

        __syncthreads();

        #pragma unroll
        for (int mf = 0; mf < 2; ++mf) {
            const int r = wm * 2 + mf;
            float* orow = out + (size_t)img * 64 * PIX +
                          (size_t)(oh0 + r) * WW + ow0;
            #pragma unroll
            for (int nf = 0; nf < 4; ++nf) {
                const int cob = wc * 32 + nf * 8 + tg * 2;
                float* r0 = orow + (size_t)cob * PIX;
                float* r1 = orow + (size_t)(cob + 1) * PIX;
                r0[g8]     = acc[mf][nf][0] + bv[nf][0];
                r1[g8]     = acc[mf][nf][1] + bv[nf][1];
                r0[g8 + 8] = acc[mf][nf][2] + bv[nf][0];
                r1[g8 + 8] = acc[mf][nf][3] + bv[nf][1];
            }
        }
    }
}

// ---------------------------------------------------------------------------
extern "C" void kernel_launch(void* const* d_in, const int* in_sizes, int n_in,
                              void* d_out, int out_size) {
    const float* x    = (const float*)d_in[0];
    const float* w    = (const float*)d_in[1];
    const float* bias = (const float*)d_in[2];
    float* out        = (float*)d_out;

    void *pxt, *pwk;
    cudaGetSymbolAddress(&pxt, g_xt);
    cudaGetSymbolAddress(&pwk, g_wk);
    __nv_bfloat16* xt = (__nv_bfloat16*)pxt;
    __nv_bfloat16* wk = (__nv_bfloat16*)pwk;

    cudaFuncSetAttribute(fused_pre_kernel,
                         cudaFuncAttributeMaxDynamicSharedMemorySize,
                         QT_SMEM);
    fused_pre_kernel<<<X_BLOCKS + 4, 256, QT_SMEM>>>(
        (const float4*)x, (const float4*)w, xt, wk);

    cudaFuncSetAttribute(conv_mma_kernel,
                         cudaFuncAttributeMaxDynamicSharedMemorySize,
                         CONV_SMEM);
    conv_mma_kernel<<<148, 512, CONV_SMEM>>>(xt, wk, bias, out);
}